// round 9
// baseline (speedup 1.0000x reference)
#include <cuda_runtime.h>
#include <stdint.h>

// Problem shape (fixed by the dataset): B=1, N=100000, E=3200000, H=8, D=64
#define NN 100000
#define HH 8
#define DD 64
#define EE 3200000
#define TOT (EE*HH)          // 25,600,000 outputs
#define NWORDS (TOT/32)      // 800,000 packed mask words

#define GRID2 1184           // 8 CTAs/SM * 148 SM (F2 total)
#define D2 768               // F2: [0,D2) edge_max CTAs, [D2,GRID2) mask CTAs
#define MW2 ((GRID2 - D2) * 8)

#define DOTS_GRID 1184
#define DOTS_UN 8

// Scratch (static device arrays). 16B-aligned for vec I/O.
__device__ __align__(16) float    g_a_self[NN*HH];
__device__ __align__(16) float    g_a_adjc[NN*HH];
__device__ __align__(16) unsigned g_M[NN*HH];     // order-encoded per-(target,head) max
__device__ __align__(16) float    g_Q[NN*HH];     // 2*exp(-leaky(a_self+maxdec))
__device__ __align__(16) unsigned g_mask[NWORDS]; // packed keep bits

// ---------------------------------------------------------------------------
// Threefry-2x32 (20 rounds), key=(0,42), ctr=(0,j), JAX partitionable:
//   bits(j) = x0 ^ x1 ;  keep(j) = bit31 == 0.
// Adds forced onto the IMAD (fma) pipe via mad.lo.u32 with an opaque 'one' so
// the alu pipe carries only the mandatory SHF+LOP3 (40 warp-ops/eval).
// ---------------------------------------------------------------------------
__device__ __forceinline__ unsigned addm(unsigned a, unsigned one, unsigned b) {
  unsigned d;
  asm("mad.lo.u32 %0, %1, %2, %3;" : "=r"(d) : "r"(a), "r"(one), "r"(b));
  return d;
}
__device__ __forceinline__ unsigned tf_xor(unsigned j, unsigned one) {
  const unsigned K1  = 42u;
  const unsigned KS2 = 0x1BD11BDAu ^ 42u;
  unsigned x0 = 0u;                 // c0(=0) + ks0(=0)
  unsigned x1 = addm(j, one, K1);   // c1 + ks1
#define TF_R(r) { x0 = addm(x1, one, x0); x1 = __funnelshift_l(x1, x1, (r)); x1 ^= x0; }
  TF_R(13) TF_R(15) TF_R(26) TF_R(6)
  x0 = addm(one, K1, x0);   x1 = addm(one, KS2 + 1u, x1);
  TF_R(17) TF_R(29) TF_R(16) TF_R(24)
  x0 = addm(one, KS2, x0);  x1 = addm(one, 2u, x1);
  TF_R(13) TF_R(15) TF_R(26) TF_R(6)
  /* ks0 = 0 */             x1 = addm(one, K1 + 3u, x1);
  TF_R(17) TF_R(29) TF_R(16) TF_R(24)
  x0 = addm(one, K1, x0);   x1 = addm(one, KS2 + 4u, x1);
  TF_R(13) TF_R(15) TF_R(26) TF_R(6)
  x0 = addm(one, KS2, x0);  x1 = addm(one, 5u, x1);
#undef TF_R
  return x0 ^ x1;
}

// Order-preserving float<->uint encoding for atomicMax
__device__ __forceinline__ unsigned enc_f(float f) {
  unsigned u = __float_as_uint(f);
  return (u & 0x80000000u) ? ~u : (u | 0x80000000u);
}
__device__ __forceinline__ float dec_f(unsigned k) {
  unsigned u = (k & 0x80000000u) ? (k ^ 0x80000000u) : ~k;
  return __uint_as_float(u);
}

__device__ __forceinline__ float leaky(float x) {
  return fmaxf(x, 0.2f * x);   // valid for all x (0.2x >= x for x<0)
}

// ---------------------------------------------------------------------------
// K1: pure dots (einsum 'nhd,dh->nh') + g_M zero-init.
// Warp per head, 8-node unroll, unpredicated main loop + guarded tail.
// ---------------------------------------------------------------------------
__global__ void k_dots(const float* __restrict__ X,
                       const float* __restrict__ Ws,
                       const float* __restrict__ Wa) {
  int w = threadIdx.x >> 5;   // head
  int l = threadIdx.x & 31;
  float ws0 = Ws[(2*l    ) * HH + w];
  float ws1 = Ws[(2*l + 1) * HH + w];
  float wa0 = Wa[(2*l    ) * HH + w];
  float wa1 = Wa[(2*l + 1) * HH + w];

  int n0 = blockIdx.x * DOTS_UN;
  for (; n0 + DOTS_UN <= NN; n0 += DOTS_GRID * DOTS_UN) {
    float2 x[DOTS_UN];
#pragma unroll
    for (int u = 0; u < DOTS_UN; u++)
      x[u] = *reinterpret_cast<const float2*>(
          X + ((size_t)(n0 + u) * HH + w) * DD + 2*l);
    float ds[DOTS_UN], da[DOTS_UN];
#pragma unroll
    for (int u = 0; u < DOTS_UN; u++) {
      ds[u] = x[u].x * ws0 + x[u].y * ws1;
      da[u] = x[u].x * wa0 + x[u].y * wa1;
    }
#pragma unroll
    for (int o = 16; o; o >>= 1)
#pragma unroll
      for (int u = 0; u < DOTS_UN; u++) {
        ds[u] += __shfl_down_sync(0xFFFFFFFFu, ds[u], o);
        da[u] += __shfl_down_sync(0xFFFFFFFFu, da[u], o);
      }
    if (l == 0)
#pragma unroll
      for (int u = 0; u < DOTS_UN; u++) {
        g_a_self[(n0 + u)*HH + w] = ds[u];
        g_a_adjc[(n0 + u)*HH + w] = da[u];
      }
    if (w == 0 && l < 8) {              // fold g_M zero-init (8 heads via lanes)
#pragma unroll
      for (int u = 0; u < DOTS_UN; u++)
        g_M[(n0 + u)*8 + l] = 0u;
    }
  }
  // tail (< DOTS_UN nodes)
  for (; n0 < NN; n0++) {
    float2 x = *reinterpret_cast<const float2*>(
        X + ((size_t)n0 * HH + w) * DD + 2*l);
    float ds = x.x * ws0 + x.y * ws1;
    float da = x.x * wa0 + x.y * wa1;
#pragma unroll
    for (int o = 16; o; o >>= 1) {
      ds += __shfl_down_sync(0xFFFFFFFFu, ds, o);
      da += __shfl_down_sync(0xFFFFFFFFu, da, o);
    }
    if (l == 0) {
      g_a_self[n0*HH + w] = ds;
      g_a_adjc[n0*HH + w] = da;
    }
    if (w == 0 && l < 8) g_M[n0*8 + l] = 0u;
  }
}

// ---------------------------------------------------------------------------
// F2: CTA-role split.
//   bid <  D2 : segment max (filtered atomics)  — L2/latency-bound, low issue
//   bid >= D2 : FULL mask generation            — alu-bound, hides under it
// ---------------------------------------------------------------------------
__global__ void k_f2(const int* __restrict__ targets,
                     const int* __restrict__ sources,
                     unsigned one) {
  if (blockIdx.x >= D2) {
    // mask role: 2 words per iteration (2 independent threefry chains)
    unsigned lane  = threadIdx.x & 31u;
    unsigned mwarp = ((blockIdx.x - D2) * 256 + threadIdx.x) >> 5;
    for (unsigned w = 2u*mwarp; w < (unsigned)NWORDS; w += 2u*MW2) {
      unsigned jA = w * 32u + lane;
      unsigned bitsA = tf_xor(jA, one);
      unsigned bitsB = tf_xor(jA + 32u, one);
      unsigned wordA = __ballot_sync(0xFFFFFFFFu, (bitsA & 0x80000000u) == 0u);
      unsigned wordB = __ballot_sync(0xFFFFFFFFu, (bitsB & 0x80000000u) == 0u);
      if (lane == 0)
        *reinterpret_cast<uint2*>(g_mask + w) = make_uint2(wordA, wordB);
    }
    return;
  }
  for (int e = blockIdx.x * 256 + threadIdx.x; e < EE; e += D2 * 256) {
    int t = targets[e];
    int s = sources[e];
    const float4 a0 = *reinterpret_cast<const float4*>(g_a_adjc + s*8);
    const float4 a1 = *reinterpret_cast<const float4*>(g_a_adjc + s*8 + 4);
    const uint4  m0 = *reinterpret_cast<const uint4 *>(g_M + t*8);
    const uint4  m1 = *reinterpret_cast<const uint4 *>(g_M + t*8 + 4);
    unsigned v;
    v = enc_f(a0.x); if (v > m0.x) atomicMax(&g_M[t*8 + 0], v);
    v = enc_f(a0.y); if (v > m0.y) atomicMax(&g_M[t*8 + 1], v);
    v = enc_f(a0.z); if (v > m0.z) atomicMax(&g_M[t*8 + 2], v);
    v = enc_f(a0.w); if (v > m0.w) atomicMax(&g_M[t*8 + 3], v);
    v = enc_f(a1.x); if (v > m1.x) atomicMax(&g_M[t*8 + 4], v);
    v = enc_f(a1.y); if (v > m1.y) atomicMax(&g_M[t*8 + 5], v);
    v = enc_f(a1.z); if (v > m1.z) atomicMax(&g_M[t*8 + 6], v);
    v = enc_f(a1.w); if (v > m1.w) atomicMax(&g_M[t*8 + 7], v);
  }
}

// ---------------------------------------------------------------------------
// K3: Q[i] = 2*exp(-leaky(a_self[i] + dec(M[i]))) per (node,head).
// Nodes with no incoming edges get junk (dec(0)=NaN) but are never gathered.
// ---------------------------------------------------------------------------
__global__ void k_prep() {
  int i4 = blockIdx.x * blockDim.x + threadIdx.x;   // over NN*HH/4
  if (i4 >= NN*HH/4) return;
  float4 as = *reinterpret_cast<const float4*>(g_a_self + 4*i4);
  uint4  me = *reinterpret_cast<const uint4 *>(g_M     + 4*i4);
  float4 q;
  q.x = 2.0f * __expf(-leaky(as.x + dec_f(me.x)));
  q.y = 2.0f * __expf(-leaky(as.y + dec_f(me.y)));
  q.z = 2.0f * __expf(-leaky(as.z + dec_f(me.z)));
  q.w = 2.0f * __expf(-leaky(as.w + dec_f(me.w)));
  *reinterpret_cast<float4*>(g_Q + 4*i4) = q;
}

// ---------------------------------------------------------------------------
// K4: one thread per EDGE (8 outputs).
//   out[e,h] = keepbit ? Q[t,h] * exp(leaky(a_self[t,h] + a_adjc[s,h])) : 0
// Mask byte from packed words; pure memory kernel (no threefry).
// ---------------------------------------------------------------------------
__global__ void k_out(const int* __restrict__ targets,
                      const int* __restrict__ sources,
                      float* __restrict__ out) {
  unsigned e = blockIdx.x * blockDim.x + threadIdx.x;
  if (e >= (unsigned)EE) return;

  unsigned word = g_mask[e >> 2];
  unsigned bits = word >> ((e & 3u) * 8u);   // 8 keep bits for this edge

  int t = targets[e];
  int s = sources[e];
  float4 as0 = *reinterpret_cast<const float4*>(g_a_self + t*8);
  float4 as1 = *reinterpret_cast<const float4*>(g_a_self + t*8 + 4);
  float4 aa0 = *reinterpret_cast<const float4*>(g_a_adjc + s*8);
  float4 aa1 = *reinterpret_cast<const float4*>(g_a_adjc + s*8 + 4);
  float4 q0  = *reinterpret_cast<const float4*>(g_Q      + t*8);
  float4 q1  = *reinterpret_cast<const float4*>(g_Q      + t*8 + 4);

  float4 o0, o1;
  o0.x = (bits & 0x01u) ? q0.x * __expf(leaky(as0.x + aa0.x)) : 0.0f;
  o0.y = (bits & 0x02u) ? q0.y * __expf(leaky(as0.y + aa0.y)) : 0.0f;
  o0.z = (bits & 0x04u) ? q0.z * __expf(leaky(as0.z + aa0.z)) : 0.0f;
  o0.w = (bits & 0x08u) ? q0.w * __expf(leaky(as0.w + aa0.w)) : 0.0f;
  o1.x = (bits & 0x10u) ? q1.x * __expf(leaky(as1.x + aa1.x)) : 0.0f;
  o1.y = (bits & 0x20u) ? q1.y * __expf(leaky(as1.y + aa1.y)) : 0.0f;
  o1.z = (bits & 0x40u) ? q1.z * __expf(leaky(as1.z + aa1.z)) : 0.0f;
  o1.w = (bits & 0x80u) ? q1.w * __expf(leaky(as1.w + aa1.w)) : 0.0f;

  *reinterpret_cast<float4*>(out + (size_t)e*8)     = o0;
  *reinterpret_cast<float4*>(out + (size_t)e*8 + 4) = o1;
}

// ---------------------------------------------------------------------------
extern "C" void kernel_launch(void* const* d_in, const int* in_sizes, int n_in,
                              void* d_out, int out_size) {
  const float* X  = (const float*)d_in[0];
  const float* Ws = (const float*)d_in[1];
  const float* Wa = (const float*)d_in[2];
  // input order: X, Wself, Wadjc, [N scalar], targets, sources, degree
  int ti = (n_in >= 6 && in_sizes[3] == 1) ? 4 : 3;
  const int* targets = (const int*)d_in[ti];
  const int* sources = (const int*)d_in[ti + 1];
  float* out = (float*)d_out;

  k_dots<<<DOTS_GRID, 256>>>(X, Ws, Wa);
  k_f2  <<<GRID2, 256>>>(targets, sources, 1u);
  k_prep<<<(NN*HH/4 + 255) / 256, 256>>>();
  k_out <<<(EE + 255) / 256, 256>>>(targets, sources, out);
}